// round 16
// baseline (speedup 1.0000x reference)
#include <cuda_runtime.h>
#include <cuda_bf16.h>
#include <cstdint>

// Problem constants
#define BATCH 2
#define LSEQ  2048
#define DMODEL 1024
#define NH 16
#define FD 16
#define HD 64
#define ROWS (BATCH*LSEQ)          // 4096
#define QKC  (NH*FD)               // 256
#define VC   (NH*HD)               // 1024

// Scratch (device globals; no allocation allowed)
__device__ float g_Q[ROWS*QKC];
__device__ float g_K[ROWS*QKC];
__device__ float g_V[ROWS*VC];
__device__ float g_Y[ROWS*VC];
__device__ float g_Z[BATCH*NH*LSEQ];          // normalizer per (b,h,l)
__device__ float g_CUM[BATCH*NH*LSEQ*FD];     // cumsum(k) per (b,h,l,f)

// ---------------------------------------------------------------------------
// SGEMM: C[M,N] = A[M,K] * B[K,N], fp32, 128x128 tile, BK=8, 256 threads,
// 8x8 register microtile. STRICT SEQUENTIAL FMA LEFT-FOLD over k.
// R10/R13 calibration (splitK2 -> 1.22*sigma, mul+add -> sqrt(2)*sigma, both
// fitting sigma=3.6e-2) proves this fold shares the reference GEMM's rounding
// path essentially bit-exactly. DO NOT PERTURB.
// ---------------------------------------------------------------------------
__global__ __launch_bounds__(256) void sgemm128(
    const float* __restrict__ A, const float* __restrict__ B,
    float* __restrict__ C, int M, int N, int K)
{
    __shared__ float As[8][128];
    __shared__ float Bs[8][128];

    const int bx = blockIdx.x;      // N tile
    const int by = blockIdx.y;      // M tile
    const int tid = threadIdx.x;
    const int tx = tid & 15;        // 16 threads across N
    const int ty = tid >> 4;        // 16 threads down M

    const int a_row = tid >> 1;          // 0..127
    const int a_col = (tid & 1) * 4;     // 0 or 4
    const int b_row = tid >> 6;          // 0..3 (each thread loads 2 rows)
    const int b_col = (tid & 63) * 2;    // float2 along N

    const float* Ap = A + (size_t)(by*128 + a_row)*K + a_col;
    const float* Bp = B + (size_t)b_row*N + (size_t)bx*128 + b_col;

    float acc[8][8];
    #pragma unroll
    for (int i=0;i<8;i++)
        #pragma unroll
        for (int j=0;j<8;j++) acc[i][j] = 0.f;

    for (int k0 = 0; k0 < K; k0 += 8) {
        float4 av = *(const float4*)(Ap + k0);
        As[a_col+0][a_row] = av.x;
        As[a_col+1][a_row] = av.y;
        As[a_col+2][a_row] = av.z;
        As[a_col+3][a_row] = av.w;
        {
            const float* p0 = Bp + (size_t)k0*N;
            float2 bv0 = *(const float2*)(p0);
            float2 bv1 = *(const float2*)(p0 + (size_t)4*N);
            Bs[b_row  ][b_col  ] = bv0.x;
            Bs[b_row  ][b_col+1] = bv0.y;
            Bs[b_row+4][b_col  ] = bv1.x;
            Bs[b_row+4][b_col+1] = bv1.y;
        }
        __syncthreads();

        #pragma unroll
        for (int kk = 0; kk < 8; ++kk) {
            float ar[8], br[8];
            float4 a0 = *(const float4*)&As[kk][ty*8];
            float4 a1 = *(const float4*)&As[kk][ty*8+4];
            ar[0]=a0.x; ar[1]=a0.y; ar[2]=a0.z; ar[3]=a0.w;
            ar[4]=a1.x; ar[5]=a1.y; ar[6]=a1.z; ar[7]=a1.w;
            float4 b0 = *(const float4*)&Bs[kk][tx*8];
            float4 b1 = *(const float4*)&Bs[kk][tx*8+4];
            br[0]=b0.x; br[1]=b0.y; br[2]=b0.z; br[3]=b0.w;
            br[4]=b1.x; br[5]=b1.y; br[6]=b1.z; br[7]=b1.w;
            #pragma unroll
            for (int i=0;i<8;i++)
                #pragma unroll
                for (int j=0;j<8;j++)
                    acc[i][j] = fmaf(ar[i], br[j], acc[i][j]);
        }
        __syncthreads();
    }

    #pragma unroll
    for (int i=0;i<8;i++) {
        float* cp = C + (size_t)(by*128 + ty*8 + i)*N + bx*128 + tx*8;
        float4 c0 = make_float4(acc[i][0],acc[i][1],acc[i][2],acc[i][3]);
        float4 c1 = make_float4(acc[i][4],acc[i][5],acc[i][6],acc[i][7]);
        *(float4*)(cp)   = c0;
        *(float4*)(cp+4) = c1;
    }
}

// ---------------------------------------------------------------------------
// Cumsum replicating XLA's ReduceWindowRewriter (base_length = 16) as applied
// to a length-2048 cumulative reduce_window:
//   Level 1: 128 chunks of 16. local1[j][r] = seq fold of e[16j..16j+r]
//            (naive per-output short cumulative window == prefix-fold bits).
//            sums1[j] = local1[j][15].
//   Outer exclusive scan over sums1 (128 > 16 -> recurse):
//     Level 2: 8 chunks of 16 over sums1. local2[u][t] = seq fold.
//              sums2[u] = local2[u][15].
//     E2[u]  = seq exclusive fold of sums2 (E2[0]=0, running fadd).
//     incl1[j = 16u+t] = fadd(E2[u], local2[u][t])   (inclusive of sums1)
//     EX1[0] = 0; EX1[j] = incl1[j-1]                (shift to exclusive)
//   Final: cum[16j+r] = fadd(EX1[j], local1[j][r])   (broadcast add)
// fl(a+b) is symmetric in operand order, so only this association matters.
// One CTA per (b,h): grid = 32, 256 threads.
// ---------------------------------------------------------------------------
__global__ __launch_bounds__(256) void rwscan_kernel(
    const float* __restrict__ K, float* __restrict__ CUM)
{
    __shared__ float s_sums1[FD][128];   // level-1 chunk sums
    __shared__ float s_ex1[FD][129];     // EX1[j] (exclusive carries), 128 used

    const int bh = blockIdx.x;
    const int b = bh / NH, h = bh % NH;
    const int tid = threadIdx.x;

    const float* kp = K + (size_t)(b*LSEQ)*QKC + h*FD;
    float* cp = CUM + (size_t)bh*LSEQ*FD;

    // Phase A: level-1 local prefixes (written to CUM) + chunk sums
    for (int idx = tid; idx < FD*128; idx += 256) {
        const int f = idx & 15;
        const int j = idx >> 4;
        float acc = 0.f;
        #pragma unroll
        for (int r = 0; r < 16; r++) {
            const int l = j*16 + r;
            acc = __fadd_rn(acc, kp[(size_t)l*QKC + f]);
            cp[(size_t)l*FD + f] = acc;               // local1 prefix
        }
        s_sums1[f][j] = acc;
    }
    __syncthreads();

    // Phases B/C/D: recursive exclusive scan of the 128 chunk sums, per f.
    if (tid < FD) {
        const int f = tid;
        float E2 = 0.f;                                // exclusive level-2 carry
        for (int u = 0; u < 8; u++) {
            float acc2 = 0.f;                          // local2 fold
            #pragma unroll
            for (int t = 0; t < 16; t++) {
                const int j = u*16 + t;
                acc2 = __fadd_rn(acc2, s_sums1[f][j]);
                s_ex1[f][j+1] = __fadd_rn(E2, acc2);   // incl1[j] -> EX1[j+1]
            }
            E2 = __fadd_rn(E2, acc2);                  // fold chunk sum (bit == sums2 fold)
        }
        s_ex1[f][0] = 0.f;
    }
    __syncthreads();

    // Phase E: broadcast-add carries onto level-1 prefixes
    for (int idx = tid; idx < FD*128; idx += 256) {
        const int f = idx & 15;
        const int j = idx >> 4;
        const float carry = s_ex1[f][j];
        if (j == 0) continue;                          // fadd(0,x)==x exact
        #pragma unroll
        for (int r = 0; r < 16; r++) {
            const int l = j*16 + r;
            const size_t a = (size_t)l*FD + f;
            cp[a] = __fadd_rn(carry, cp[a]);
        }
    }
}

// ---------------------------------------------------------------------------
// z[bh,l] = 1 / (sum_{f=0..15} fl(q_f * cum_f) + 1e-12).
// Separate __fmul_rn/__fadd_rn sequential fold: XLA fuses the elementwise mul
// (producer) with the row-reduce (combiner add) as distinct ops, and LLVM
// does not contract them without fast-math flags.
// ---------------------------------------------------------------------------
__global__ __launch_bounds__(256) void zdot_kernel(
    const float* __restrict__ Q, const float* __restrict__ CUM,
    float* __restrict__ Z)
{
    const int idx = blockIdx.x * 256 + threadIdx.x;   // bh*LSEQ + l
    const int bh = idx >> 11;
    const int l  = idx & (LSEQ-1);
    const int b = bh / NH, h = bh % NH;

    const float4* qp = (const float4*)(Q + (size_t)(b*LSEQ + l)*QKC + h*FD);
    const float4* cp = (const float4*)(CUM + ((size_t)bh*LSEQ + l)*FD);
    float q[16], c[16];
    #pragma unroll
    for (int i=0;i<4;i++) {
        float4 qv = qp[i], cv = cp[i];
        q[4*i+0]=qv.x; q[4*i+1]=qv.y; q[4*i+2]=qv.z; q[4*i+3]=qv.w;
        c[4*i+0]=cv.x; c[4*i+1]=cv.y; c[4*i+2]=cv.z; c[4*i+3]=cv.w;
    }

    float acc = 0.f;                      // strict f = 0..15 fold, no fma
    #pragma unroll
    for (int f=0; f<16; f++)
        acc = __fadd_rn(acc, __fmul_rn(q[f], c[f]));

    Z[idx] = 1.f / __fadd_rn(acc, 1e-12f);
}

// ---------------------------------------------------------------------------
// Chunked causal linear attention (NUMERATOR only; z is precomputed).
// One CTA per (b,h). State S[16][64] carried across chunks of 64 tokens.
// 256 threads: thread handles token t = tid/4, v-dim quarter tid%4.
// ---------------------------------------------------------------------------
#define CT 64
__global__ __launch_bounds__(256) void attn_kernel(
    const float* __restrict__ Q, const float* __restrict__ K,
    const float* __restrict__ V, const float* __restrict__ Z,
    float* __restrict__ Y)
{
    __shared__ float sq[CT][17];
    __shared__ float sk[CT][17];
    __shared__ float sv[CT][HD];
    __shared__ float S[FD][HD];

    const int bh = blockIdx.x;
    const int b = bh / NH;
    const int h = bh % NH;
    const int tid = threadIdx.x;

    for (int i = tid; i < FD*HD; i += 256) ((float*)S)[i] = 0.f;
    __syncthreads();

    const int t  = tid >> 2;
    const int qd = (tid & 3) * 16;

    for (int c0 = 0; c0 < LSEQ; c0 += CT) {
        // ---- load chunk ----
        for (int i = tid; i < CT*FD; i += 256) {
            int l = c0 + (i >> 4), f = i & 15;
            size_t base = (size_t)(b*LSEQ + l)*QKC + h*FD + f;
            sq[i>>4][f] = Q[base];
            sk[i>>4][f] = K[base];
        }
        for (int i = tid; i < CT*HD; i += 256) {
            int l = c0 + (i >> 6), d = i & 63;
            sv[i>>6][d] = V[(size_t)(b*LSEQ + l)*VC + h*HD + d];
        }
        __syncthreads();

        // ---- numerator for my token / quarter ----
        float qreg[FD];
        #pragma unroll
        for (int f=0; f<FD; f++) qreg[f] = sq[t][f];

        float acc[16];
        #pragma unroll
        for (int d=0; d<16; d++) acc[d] = 0.f;

        // inter-chunk contribution via state
        #pragma unroll
        for (int f=0; f<FD; f++) {
            #pragma unroll
            for (int d=0; d<16; d++)
                acc[d] = fmaf(qreg[f], S[f][qd+d], acc[d]);
        }
        // intra-chunk causal contribution
        for (int m=0; m<=t; m++) {
            float a = 0.f;
            #pragma unroll
            for (int f=0; f<FD; f++) a = fmaf(qreg[f], sk[m][f], a);
            #pragma unroll
            for (int d=0; d<16; d++)
                acc[d] = fmaf(a, sv[m][qd+d], acc[d]);
        }

        // ---- apply normalizer, write out ----
        {
            int l = c0 + t;
            const float z = Z[(size_t)bh*LSEQ + l];
            float* yp = Y + (size_t)(b*LSEQ + l)*VC + h*HD + qd;
            #pragma unroll
            for (int d=0; d<16; d+=4) {
                float4 v4 = make_float4(acc[d]*z, acc[d+1]*z, acc[d+2]*z, acc[d+3]*z);
                *(float4*)(yp + d) = v4;
            }
        }
        __syncthreads();   // S still being read above

        // ---- update state with this chunk ----
        for (int i = tid; i < FD*HD; i += 256) {
            int f = i >> 6, d = i & 63;
            float s = 0.f;
            #pragma unroll 8
            for (int m=0; m<CT; m++) s = fmaf(sk[m][f], sv[m][d], s);
            S[f][d] += s;
        }
        __syncthreads();
    }
}

// ---------------------------------------------------------------------------
extern "C" void kernel_launch(void* const* d_in, const int* in_sizes, int n_in,
                              void* d_out, int out_size)
{
    const float* X  = (const float*)d_in[0];   // (2,2048,1024)
    const float* Wq = (const float*)d_in[1];   // (1024,256)
    const float* Wk = (const float*)d_in[2];   // (1024,256)
    const float* Wv = (const float*)d_in[3];   // (1024,1024)
    const float* Wo = (const float*)d_in[4];   // (1024,1024)
    float* out = (float*)d_out;                // (2,2048,1024)

    float *Qb, *Kb, *Vb, *Yb, *Zb, *Cb;
    cudaGetSymbolAddress((void**)&Qb, g_Q);
    cudaGetSymbolAddress((void**)&Kb, g_K);
    cudaGetSymbolAddress((void**)&Vb, g_V);
    cudaGetSymbolAddress((void**)&Yb, g_Y);
    cudaGetSymbolAddress((void**)&Zb, g_Z);
    cudaGetSymbolAddress((void**)&Cb, g_CUM);

    dim3 blk(256);
    // QKV projections: strict fma fold (calibrated as bit-matching the ref)
    sgemm128<<<dim3(QKC/128, ROWS/128), blk>>>(X, Wq, Qb, ROWS, QKC, DMODEL);
    sgemm128<<<dim3(QKC/128, ROWS/128), blk>>>(X, Wk, Kb, ROWS, QKC, DMODEL);
    sgemm128<<<dim3(VC/128,  ROWS/128), blk>>>(X, Wv, Vb, ROWS, VC, DMODEL);
    // normalizer: ReduceWindowRewriter-structured cumsum + muladd dot
    rwscan_kernel<<<dim3(BATCH*NH), blk>>>(Kb, Cb);
    zdot_kernel<<<dim3(BATCH*NH*LSEQ/256), blk>>>(Qb, Cb, Zb);
    // causal linear attention numerator + normalization
    attn_kernel<<<dim3(BATCH*NH), blk>>>(Qb, Kb, Vb, Zb, Yb);
    // output projection
    sgemm128<<<dim3(DMODEL/128, ROWS/128), blk>>>(Yb, Wo, out, ROWS, DMODEL, DMODEL);
}

// round 17
// speedup vs baseline: 1.1316x; 1.1316x over previous
#include <cuda_runtime.h>
#include <cuda_bf16.h>
#include <cstdint>

// Problem constants
#define BATCH 2
#define LSEQ  2048
#define DMODEL 1024
#define NH 16
#define FD 16
#define HD 64
#define ROWS (BATCH*LSEQ)          // 4096
#define QKC  (NH*FD)               // 256
#define VC   (NH*HD)               // 1024
#define NCHUNK 32                  // 2048 / 64
#define CT 64

// Scratch (device globals; no allocation allowed)
__device__ float g_Q[ROWS*QKC];
__device__ float g_K[ROWS*QKC];
__device__ float g_V[ROWS*VC];
__device__ float g_Y[ROWS*VC];
__device__ float g_Z[BATCH*NH*LSEQ];              // normalizer per (b,h,l)
__device__ float g_CUM[BATCH*NH*LSEQ*FD];         // cumsum(k) per (b,h,l,f)
__device__ float g_S[BATCH*NH*NCHUNK*FD*HD];      // per-chunk kv states
__device__ float g_P[BATCH*NH*NCHUNK*FD*HD];      // exclusive prefix states

// ---------------------------------------------------------------------------
// Double-buffered SGEMM core. C[M,N] = A[M,K]*B[K,N], 128x128 tile, BK=8,
// 256 threads, 8x8 microtile. Per-element accumulation is a STRICT SEQUENTIAL
// FMA LEFT-FOLD over ascending k — bitwise identical to the R16 kernel
// (buffering/pipelining does not touch the fold). DEN PATH DEPENDS ON THESE
// BITS — do not change the math order.
// ---------------------------------------------------------------------------
__device__ __forceinline__ void sgemm_db_body(
    const float* __restrict__ A, const float* __restrict__ B,
    float* __restrict__ C, int N, int K, int bx, int by)
{
    __shared__ float As[2][8][128];
    __shared__ float Bs[2][8][132];

    const int tid = threadIdx.x;
    const int tx = tid & 15;             // 16 threads across N
    const int ty = tid >> 4;             // 16 threads down M

    const int a_row = tid >> 1;          // 0..127
    const int a_col = (tid & 1) * 4;     // 0 or 4
    const int b_row = tid >> 5;          // 0..7
    const int b_col = (tid & 31) * 4;    // 0..124 step 4

    const float* Ap = A + (size_t)(by*128 + a_row)*K + a_col;
    const float* Bp = B + (size_t)b_row*N + (size_t)bx*128 + b_col;

    float acc[8][8];
    #pragma unroll
    for (int i=0;i<8;i++)
        #pragma unroll
        for (int j=0;j<8;j++) acc[i][j] = 0.f;

    // preload stage 0
    float4 av = *(const float4*)(Ap);
    float4 bv = *(const float4*)(Bp);
    As[0][a_col+0][a_row] = av.x;
    As[0][a_col+1][a_row] = av.y;
    As[0][a_col+2][a_row] = av.z;
    As[0][a_col+3][a_row] = av.w;
    *(float4*)&Bs[0][b_row][b_col] = bv;
    __syncthreads();

    const int T = K / 8;
    for (int kt = 0; kt < T; kt++) {
        const int cur = kt & 1;
        if (kt + 1 < T) {   // prefetch next tile into registers
            av = *(const float4*)(Ap + (kt+1)*8);
            bv = *(const float4*)(Bp + (size_t)(kt+1)*8*N);
        }
        #pragma unroll
        for (int kk = 0; kk < 8; ++kk) {
            float ar[8], br[8];
            float4 a0 = *(const float4*)&As[cur][kk][ty*8];
            float4 a1 = *(const float4*)&As[cur][kk][ty*8+4];
            ar[0]=a0.x; ar[1]=a0.y; ar[2]=a0.z; ar[3]=a0.w;
            ar[4]=a1.x; ar[5]=a1.y; ar[6]=a1.z; ar[7]=a1.w;
            float4 b0 = *(const float4*)&Bs[cur][kk][tx*8];
            float4 b1 = *(const float4*)&Bs[cur][kk][tx*8+4];
            br[0]=b0.x; br[1]=b0.y; br[2]=b0.z; br[3]=b0.w;
            br[4]=b1.x; br[5]=b1.y; br[6]=b1.z; br[7]=b1.w;
            #pragma unroll
            for (int i=0;i<8;i++)
                #pragma unroll
                for (int j=0;j<8;j++)
                    acc[i][j] = fmaf(ar[i], br[j], acc[i][j]);
        }
        if (kt + 1 < T) {
            const int nxt = cur ^ 1;
            As[nxt][a_col+0][a_row] = av.x;
            As[nxt][a_col+1][a_row] = av.y;
            As[nxt][a_col+2][a_row] = av.z;
            As[nxt][a_col+3][a_row] = av.w;
            *(float4*)&Bs[nxt][b_row][b_col] = bv;
            __syncthreads();
        }
    }

    #pragma unroll
    for (int i=0;i<8;i++) {
        float* cp = C + (size_t)(by*128 + ty*8 + i)*N + bx*128 + tx*8;
        float4 c0 = make_float4(acc[i][0],acc[i][1],acc[i][2],acc[i][3]);
        float4 c1 = make_float4(acc[i][4],acc[i][5],acc[i][6],acc[i][7]);
        *(float4*)(cp)   = c0;
        *(float4*)(cp+4) = c1;
    }
}

// Plain GEMM launch wrapper
__global__ __launch_bounds__(256) void sgemm_db(
    const float* __restrict__ A, const float* __restrict__ B,
    float* __restrict__ C, int N, int K)
{
    sgemm_db_body(A, B, C, N, K, blockIdx.x, blockIdx.y);
}

// Fused Q+K projection: blockIdx.z selects (Wq->Q) or (Wk->K).
__global__ __launch_bounds__(256) void qkgemm_db(
    const float* __restrict__ X,
    const float* __restrict__ Wq, const float* __restrict__ Wk,
    float* __restrict__ Q, float* __restrict__ Kout)
{
    const float* B = (blockIdx.z == 0) ? Wq : Wk;
    float* C       = (blockIdx.z == 0) ? Q  : Kout;
    sgemm_db_body(X, B, C, QKC, DMODEL, blockIdx.x, blockIdx.y);
}

// ---------------------------------------------------------------------------
// Cumsum replicating XLA's ReduceWindowRewriter (base_length = 16) for the
// length-2048 cumulative reduce_window. VERIFIED PASSING in R16 — bit-frozen.
// One CTA per (b,h): grid = 32, 256 threads.
// ---------------------------------------------------------------------------
__global__ __launch_bounds__(256) void rwscan_kernel(
    const float* __restrict__ K, float* __restrict__ CUM)
{
    __shared__ float s_sums1[FD][128];   // level-1 chunk sums
    __shared__ float s_ex1[FD][129];     // EX1[j] (exclusive carries)

    const int bh = blockIdx.x;
    const int b = bh / NH, h = bh % NH;
    const int tid = threadIdx.x;

    const float* kp = K + (size_t)(b*LSEQ)*QKC + h*FD;
    float* cp = CUM + (size_t)bh*LSEQ*FD;

    // Phase A: level-1 local prefixes (written to CUM) + chunk sums
    for (int idx = tid; idx < FD*128; idx += 256) {
        const int f = idx & 15;
        const int j = idx >> 4;
        float acc = 0.f;
        #pragma unroll
        for (int r = 0; r < 16; r++) {
            const int l = j*16 + r;
            acc = __fadd_rn(acc, kp[(size_t)l*QKC + f]);
            cp[(size_t)l*FD + f] = acc;
        }
        s_sums1[f][j] = acc;
    }
    __syncthreads();

    // Phases B/C/D: recursive exclusive scan of the 128 chunk sums, per f.
    if (tid < FD) {
        const int f = tid;
        float E2 = 0.f;
        for (int u = 0; u < 8; u++) {
            float acc2 = 0.f;
            #pragma unroll
            for (int t = 0; t < 16; t++) {
                const int j = u*16 + t;
                acc2 = __fadd_rn(acc2, s_sums1[f][j]);
                s_ex1[f][j+1] = __fadd_rn(E2, acc2);
            }
            E2 = __fadd_rn(E2, acc2);
        }
        s_ex1[f][0] = 0.f;
    }
    __syncthreads();

    // Phase E: broadcast-add carries onto level-1 prefixes
    for (int idx = tid; idx < FD*128; idx += 256) {
        const int f = idx & 15;
        const int j = idx >> 4;
        const float carry = s_ex1[f][j];
        if (j == 0) continue;
        #pragma unroll
        for (int r = 0; r < 16; r++) {
            const int l = j*16 + r;
            const size_t a = (size_t)l*FD + f;
            cp[a] = __fadd_rn(carry, cp[a]);
        }
    }
}

// ---------------------------------------------------------------------------
// z[bh,l] = 1 / (sum_{f=0..15} fl(q_f * cum_f) + 1e-12).
// Separate mul/add sequential fold. VERIFIED PASSING in R16 — bit-frozen.
// ---------------------------------------------------------------------------
__global__ __launch_bounds__(256) void zdot_kernel(
    const float* __restrict__ Q, const float* __restrict__ CUM,
    float* __restrict__ Z)
{
    const int idx = blockIdx.x * 256 + threadIdx.x;   // bh*LSEQ + l
    const int bh = idx >> 11;
    const int l  = idx & (LSEQ-1);
    const int b = bh / NH, h = bh % NH;

    const float4* qp = (const float4*)(Q + (size_t)(b*LSEQ + l)*QKC + h*FD);
    const float4* cp = (const float4*)(CUM + ((size_t)bh*LSEQ + l)*FD);
    float q[16], c[16];
    #pragma unroll
    for (int i=0;i<4;i++) {
        float4 qv = qp[i], cv = cp[i];
        q[4*i+0]=qv.x; q[4*i+1]=qv.y; q[4*i+2]=qv.z; q[4*i+3]=qv.w;
        c[4*i+0]=cv.x; c[4*i+1]=cv.y; c[4*i+2]=cv.z; c[4*i+3]=cv.w;
    }

    float acc = 0.f;
    #pragma unroll
    for (int f=0; f<16; f++)
        acc = __fadd_rn(acc, __fmul_rn(q[f], c[f]));

    Z[idx] = 1.f / __fadd_rn(acc, 1e-12f);
}

// ---------------------------------------------------------------------------
// Attention pass 1: per-chunk kv states.
// S[bh][c][f][d] = fma-fold_{m=0..63} k[m][f] * v[m][d]   (same bits as the
// old attn_kernel's per-chunk state contribution).
// grid (NCHUNK, BATCH*NH), 256 threads.
// ---------------------------------------------------------------------------
__global__ __launch_bounds__(256) void state_kernel(
    const float* __restrict__ K, const float* __restrict__ V,
    float* __restrict__ S)
{
    __shared__ float sk[CT][17];
    __shared__ float sv[CT][HD];

    const int c  = blockIdx.x;
    const int bh = blockIdx.y;
    const int b = bh / NH, h = bh % NH;
    const int tid = threadIdx.x;
    const int c0 = c * CT;

    for (int i = tid; i < CT*FD; i += 256) {
        int l = c0 + (i >> 4), f = i & 15;
        sk[i>>4][f] = K[(size_t)(b*LSEQ + l)*QKC + h*FD + f];
    }
    for (int i = tid; i < CT*HD; i += 256) {
        int l = c0 + (i >> 6), d = i & 63;
        sv[i>>6][d] = V[(size_t)(b*LSEQ + l)*VC + h*HD + d];
    }
    __syncthreads();

    float* sp = S + ((size_t)bh*NCHUNK + c)*FD*HD;
    for (int i = tid; i < FD*HD; i += 256) {
        int f = i >> 6, d = i & 63;
        float s = 0.f;
        #pragma unroll 8
        for (int m=0; m<CT; m++) s = fmaf(sk[m][f], sv[m][d], s);
        sp[i] = s;
    }
}

// ---------------------------------------------------------------------------
// Attention pass 2: exclusive prefix of states over chunks.
// P[c] = fold_{c'<c} (P + S[c'])  — plain fadd in ascending c order, the same
// association as the old "S += s_c" update.
// grid BATCH*NH, 256 threads.
// ---------------------------------------------------------------------------
__global__ __launch_bounds__(256) void prefix_kernel(
    const float* __restrict__ S, float* __restrict__ P)
{
    const int bh = blockIdx.x;
    const int tid = threadIdx.x;
    const size_t base = (size_t)bh*NCHUNK*FD*HD;

    for (int i = tid; i < FD*HD; i += 256) {
        float acc = 0.f;
        #pragma unroll 4
        for (int c = 0; c < NCHUNK; c++) {
            P[base + (size_t)c*FD*HD + i] = acc;
            acc += S[base + (size_t)c*FD*HD + i];
        }
    }
}

// ---------------------------------------------------------------------------
// Attention pass 3: per-chunk output (numerator * precomputed z).
// Same per-token math as the old attn_kernel body; inter-chunk state read
// from P. grid (NCHUNK, BATCH*NH), 256 threads: token t = tid/4, v-quarter.
// ---------------------------------------------------------------------------
__global__ __launch_bounds__(256) void attn_out_kernel(
    const float* __restrict__ Q, const float* __restrict__ K,
    const float* __restrict__ V, const float* __restrict__ Z,
    const float* __restrict__ P, float* __restrict__ Y)
{
    __shared__ float sq[CT][17];
    __shared__ float sk[CT][17];
    __shared__ float sv[CT][HD];
    __shared__ float S[FD][HD];

    const int c  = blockIdx.x;
    const int bh = blockIdx.y;
    const int b = bh / NH, h = bh % NH;
    const int tid = threadIdx.x;
    const int c0 = c * CT;

    for (int i = tid; i < CT*FD; i += 256) {
        int l = c0 + (i >> 4), f = i & 15;
        size_t base = (size_t)(b*LSEQ + l)*QKC + h*FD + f;
        sq[i>>4][f] = Q[base];
        sk[i>>4][f] = K[base];
    }
    for (int i = tid; i < CT*HD; i += 256) {
        int l = c0 + (i >> 6), d = i & 63;
        sv[i>>6][d] = V[(size_t)(b*LSEQ + l)*VC + h*HD + d];
    }
    {
        const float* pp = P + ((size_t)bh*NCHUNK + c)*FD*HD;
        for (int i = tid; i < FD*HD; i += 256) ((float*)S)[i] = pp[i];
    }
    __syncthreads();

    const int t  = tid >> 2;
    const int qd = (tid & 3) * 16;

    float qreg[FD];
    #pragma unroll
    for (int f=0; f<FD; f++) qreg[f] = sq[t][f];

    float acc[16];
    #pragma unroll
    for (int d=0; d<16; d++) acc[d] = 0.f;

    // inter-chunk contribution via prefix state
    #pragma unroll
    for (int f=0; f<FD; f++) {
        #pragma unroll
        for (int d=0; d<16; d++)
            acc[d] = fmaf(qreg[f], S[f][qd+d], acc[d]);
    }
    // intra-chunk causal contribution
    for (int m=0; m<=t; m++) {
        float a = 0.f;
        #pragma unroll
        for (int f=0; f<FD; f++) a = fmaf(qreg[f], sk[m][f], a);
        #pragma unroll
        for (int d=0; d<16; d++)
            acc[d] = fmaf(a, sv[m][qd+d], acc[d]);
    }

    // apply normalizer, write out
    {
        int l = c0 + t;
        const float z = Z[(size_t)bh*LSEQ + l];
        float* yp = Y + (size_t)(b*LSEQ + l)*VC + h*HD + qd;
        #pragma unroll
        for (int d=0; d<16; d+=4) {
            float4 v4 = make_float4(acc[d]*z, acc[d+1]*z, acc[d+2]*z, acc[d+3]*z);
            *(float4*)(yp + d) = v4;
        }
    }
}

// ---------------------------------------------------------------------------
extern "C" void kernel_launch(void* const* d_in, const int* in_sizes, int n_in,
                              void* d_out, int out_size)
{
    const float* X  = (const float*)d_in[0];   // (2,2048,1024)
    const float* Wq = (const float*)d_in[1];   // (1024,256)
    const float* Wk = (const float*)d_in[2];   // (1024,256)
    const float* Wv = (const float*)d_in[3];   // (1024,1024)
    const float* Wo = (const float*)d_in[4];   // (1024,1024)
    float* out = (float*)d_out;                // (2,2048,1024)

    float *Qb, *Kb, *Vb, *Yb, *Zb, *Cb, *Sb, *Pb;
    cudaGetSymbolAddress((void**)&Qb, g_Q);
    cudaGetSymbolAddress((void**)&Kb, g_K);
    cudaGetSymbolAddress((void**)&Vb, g_V);
    cudaGetSymbolAddress((void**)&Yb, g_Y);
    cudaGetSymbolAddress((void**)&Zb, g_Z);
    cudaGetSymbolAddress((void**)&Cb, g_CUM);
    cudaGetSymbolAddress((void**)&Sb, g_S);
    cudaGetSymbolAddress((void**)&Pb, g_P);

    dim3 blk(256);

    // Q+K projections fused (den-path bits identical to R16: same fold)
    qkgemm_db<<<dim3(QKC/128, ROWS/128, 2), blk>>>(X, Wq, Wk, Qb, Kb);
    // V projection
    sgemm_db<<<dim3(VC/128, ROWS/128), blk>>>(X, Wv, Vb, VC, DMODEL);
    // normalizer: ReduceWindowRewriter cumsum + muladd dot (bit-frozen)
    rwscan_kernel<<<dim3(BATCH*NH), blk>>>(Kb, Cb);
    zdot_kernel<<<dim3(BATCH*NH*LSEQ/256), blk>>>(Qb, Cb, Zb);
    // chunk-parallel causal linear attention (numerator bits preserved)
    state_kernel<<<dim3(NCHUNK, BATCH*NH), blk>>>(Kb, Vb, Sb);
    prefix_kernel<<<dim3(BATCH*NH), blk>>>(Sb, Pb);
    attn_out_kernel<<<dim3(NCHUNK, BATCH*NH), blk>>>(Qb, Kb, Vb, Zb, Pb, Yb);
    // output projection
    sgemm_db<<<dim3(DMODEL/128, ROWS/128), blk>>>(Yb, Wo, out, DMODEL, DMODEL);
}